// round 9
// baseline (speedup 1.0000x reference)
#include <cuda_runtime.h>
#include <math.h>

static const int B = 32;
static const int S = 512;
static const int R = 128;
static const int D = 64;
static const int E = 128;
static const int H = 256;
#define NROWS (32*512 + 128)   // B*S + R = 16512

typedef unsigned long long ull;

// ---------------- packed f32x2 helpers (sm_100+) ----------------------------
__device__ __forceinline__ ull fma2(ull a, ull b, ull c) {
    ull d; asm("fma.rn.f32x2 %0,%1,%2,%3;" : "=l"(d) : "l"(a), "l"(b), "l"(c));
    return d;
}
__device__ __forceinline__ ull add2(ull a, ull b) {
    ull d; asm("add.rn.f32x2 %0,%1,%2;" : "=l"(d) : "l"(a), "l"(b));
    return d;
}
__device__ __forceinline__ ull pk2(float x, float y) {
    ull d; asm("mov.b64 %0,{%1,%2};" : "=l"(d) : "f"(x), "f"(y));
    return d;
}
__device__ __forceinline__ float2 upk2(ull d) {
    float2 r; asm("mov.b64 {%0,%1},%2;" : "=f"(r.x), "=f"(r.y) : "l"(d));
    return r;
}
__device__ __forceinline__ void cp4(void* dst, const void* src) {
    unsigned d = (unsigned)__cvta_generic_to_shared(dst);
    asm volatile("cp.async.ca.shared.global [%0],[%1],4;" :: "r"(d), "l"(src));
}

// ---------------- scratch (static device globals) ---------------------------
__device__ float g_emb[NROWS * 128];                 // (B*S + R, E)
__device__ float g_Q[128 * 128];                     // Qtmp (R,E)
__device__ float g_Q2[128 * 128];                    // Q2 = Qtmp @ Wk (R,E)
__device__ float g_cb[128];                          // cb[r] = Qtmp[r].bk
__device__ float g_SC[32 * 128 * 512];               // exp(scores), (B,R,S)
__device__ float g_enc[32 * 128 * 64];               // (B,R,D)
__device__ float4 g_h[2][2][(256/4) * 32];           // [dir][parity][k4*32 + b]
__device__ int   g_bar[2];                           // per-direction step counter

// ---------------- 1) time embedding + state init ----------------------------
__global__ void k_emb(const float* __restrict__ ts, const float* __restrict__ qt,
                      const float* __restrict__ w_per, const float* __restrict__ b_per,
                      const float* __restrict__ w_lin, const float* __restrict__ b_lin)
{
    int idx = blockIdx.x * blockDim.x + threadIdx.x;
    if (idx < 2048) {                       // zero h(0) for both dirs (parity 0)
        g_h[0][0][idx] = make_float4(0.f, 0.f, 0.f, 0.f);
        g_h[1][0][idx] = make_float4(0.f, 0.f, 0.f, 0.f);
    }
    if (idx < 128) g_cb[idx] = 0.f;
    if (idx < 2)   g_bar[idx] = 0;
    if (idx >= NROWS * 128) return;
    int row = idx >> 7;
    int e   = idx & 127;
    float t = (row < B * S) ? ts[row] : qt[row - B * S];
    float v;
    if (e == 0) v = fmaf(t, w_lin[0], b_lin[0]);
    else        v = __sinf(fmaf(t, w_per[e - 1], b_per[e - 1]));
    g_emb[idx] = v;
}

// ---------------- 2) C = op(alpha*(A @ B^T + rbias[m]) + bias[n]) ------------
// op = exp() when doexp. Optionally accumulates cbout[m] += C[m,:].dotv via
// atomics (folds cb = Q.bk into the Q projection). 64x64 tile, k-chunk 16,
// 256 thr, cp.async double-buffer.
__global__ void __launch_bounds__(256)
k_gemm_nt(const float* __restrict__ Ag, const float* __restrict__ Bg,
          const float* __restrict__ bias, const float* __restrict__ rbias,
          const float* __restrict__ dotv, float* __restrict__ cbout,
          float* __restrict__ Cg,
          int Ksz, int lda, int ldb, int ldc,
          long long strideA, long long strideB, long long strideC,
          float alpha, int doexp)
{
    __shared__ float As[2][16][68];
    __shared__ float Bs[2][16][68];
    const float* A  = Ag + (long long)blockIdx.z * strideA;
    const float* Bm = Bg + (long long)blockIdx.z * strideB;
    float*       C  = Cg + (long long)blockIdx.z * strideC;
    int m0 = blockIdx.y * 64, n0 = blockIdx.x * 64;
    int tid = threadIdx.x;
    int tx = tid & 15, ty = tid >> 4;
    int k = tid & 15, v = tid >> 4;

    ull acc[4][2];
#pragma unroll
    for (int i = 0; i < 4; i++) { acc[i][0] = 0ull; acc[i][1] = 0ull; }

    int nch = Ksz >> 4;
#pragma unroll
    for (int p = 0; p < 4; p++) {
        cp4(&As[0][k][v + p * 16], &A[(long long)(m0 + v + p * 16) * lda + k]);
        cp4(&Bs[0][k][v + p * 16], &Bm[(long long)(n0 + v + p * 16) * ldb + k]);
    }
    asm volatile("cp.async.commit_group;");

    for (int i = 0; i < nch; i++) {
        if (i + 1 < nch) {
            int buf = (i + 1) & 1, kc = (i + 1) * 16;
#pragma unroll
            for (int p = 0; p < 4; p++) {
                cp4(&As[buf][k][v + p * 16], &A[(long long)(m0 + v + p * 16) * lda + kc + k]);
                cp4(&Bs[buf][k][v + p * 16], &Bm[(long long)(n0 + v + p * 16) * ldb + kc + k]);
            }
            asm volatile("cp.async.commit_group;");
            asm volatile("cp.async.wait_group 1;");
        } else {
            asm volatile("cp.async.wait_group 0;");
        }
        __syncthreads();
        int cb2 = i & 1;
#pragma unroll
        for (int kk = 0; kk < 16; kk++) {
            float4 a4 = *(const float4*)&As[cb2][kk][ty * 4];
            ulonglong2 bb = *(const ulonglong2*)&Bs[cb2][kk][tx * 4];
            ull aa;
            aa = pk2(a4.x, a4.x);
            acc[0][0] = fma2(aa, bb.x, acc[0][0]); acc[0][1] = fma2(aa, bb.y, acc[0][1]);
            aa = pk2(a4.y, a4.y);
            acc[1][0] = fma2(aa, bb.x, acc[1][0]); acc[1][1] = fma2(aa, bb.y, acc[1][1]);
            aa = pk2(a4.z, a4.z);
            acc[2][0] = fma2(aa, bb.x, acc[2][0]); acc[2][1] = fma2(aa, bb.y, acc[2][1]);
            aa = pk2(a4.w, a4.w);
            acc[3][0] = fma2(aa, bb.x, acc[3][0]); acc[3][1] = fma2(aa, bb.y, acc[3][1]);
        }
        __syncthreads();
    }
    float4 bv = make_float4(0.f, 0.f, 0.f, 0.f);
    if (bias) bv = *(const float4*)&bias[n0 + tx * 4];
    float4 dv = make_float4(0.f, 0.f, 0.f, 0.f);
    if (dotv) dv = *(const float4*)&dotv[n0 + tx * 4];
#pragma unroll
    for (int i = 0; i < 4; i++) {
        int m = m0 + ty * 4 + i;
        float rba = rbias ? rbias[m] * alpha : 0.f;
        float2 v0 = upk2(acc[i][0]), v1 = upk2(acc[i][1]);
        float4 o;
        o.x = fmaf(v0.x, alpha, bv.x + rba);
        o.y = fmaf(v0.y, alpha, bv.y + rba);
        o.z = fmaf(v1.x, alpha, bv.z + rba);
        o.w = fmaf(v1.y, alpha, bv.w + rba);
        if (dotv) {
            float p = o.x * dv.x + o.y * dv.y + o.z * dv.z + o.w * dv.w;
#pragma unroll
            for (int off = 8; off > 0; off >>= 1)
                p += __shfl_xor_sync(0xffffffffu, p, off);
            if (tx == 0) atomicAdd(&cbout[m], p);
        }
        if (doexp) {
            o.x = __expf(o.x); o.y = __expf(o.y);
            o.z = __expf(o.z); o.w = __expf(o.w);
        }
        *(float4*)&C[(long long)m * ldc + n0 + tx * 4] = o;
    }
}

// ---------------- 2b) Q2 = Qtmp @ Wk  (NN, 128x128x128, grid (2,2)) ---------
__global__ void __launch_bounds__(256)
k_nn(const float* __restrict__ A, const float* __restrict__ Bm,
     float* __restrict__ C)
{
    __shared__ float As[16][68];
    __shared__ float Bs[16][68];
    int m0 = blockIdx.y * 64, n0 = blockIdx.x * 64;
    int tid = threadIdx.x;
    int tx = tid & 15, ty = tid >> 4;

    ull acc[4][2];
#pragma unroll
    for (int i = 0; i < 4; i++) { acc[i][0] = 0ull; acc[i][1] = 0ull; }

    for (int kc = 0; kc < 128; kc += 16) {
        {
            int k = tid & 15, v = tid >> 4;
#pragma unroll
            for (int p = 0; p < 4; p++)
                As[k][v + p * 16] = A[(m0 + v + p * 16) * 128 + kc + k];
            int kr = tid >> 4, nb = (tid & 15) * 4;
            *(float4*)&Bs[kr][nb] = *(const float4*)&Bm[(kc + kr) * 128 + n0 + nb];
        }
        __syncthreads();
#pragma unroll
        for (int kk = 0; kk < 16; kk++) {
            float4 a4 = *(const float4*)&As[kk][ty * 4];
            ulonglong2 bb = *(const ulonglong2*)&Bs[kk][tx * 4];
            ull aa;
            aa = pk2(a4.x, a4.x);
            acc[0][0] = fma2(aa, bb.x, acc[0][0]); acc[0][1] = fma2(aa, bb.y, acc[0][1]);
            aa = pk2(a4.y, a4.y);
            acc[1][0] = fma2(aa, bb.x, acc[1][0]); acc[1][1] = fma2(aa, bb.y, acc[1][1]);
            aa = pk2(a4.z, a4.z);
            acc[2][0] = fma2(aa, bb.x, acc[2][0]); acc[2][1] = fma2(aa, bb.y, acc[2][1]);
            aa = pk2(a4.w, a4.w);
            acc[3][0] = fma2(aa, bb.x, acc[3][0]); acc[3][1] = fma2(aa, bb.y, acc[3][1]);
        }
        __syncthreads();
    }
#pragma unroll
    for (int i = 0; i < 4; i++) {
        int m = m0 + ty * 4 + i;
        float2 v0 = upk2(acc[i][0]), v1 = upk2(acc[i][1]);
        float4 o = make_float4(v0.x, v0.y, v1.x, v1.y);
        *(float4*)&C[m * 128 + n0 + tx * 4] = o;
    }
}

// ---------------- 3) enc_in = (e @ mask*x) / (e @ mask) ----------------------
__global__ void __launch_bounds__(256)
k_enc(const float* __restrict__ xv, const int* __restrict__ xm)
{
    __shared__ float Es[16][33];
    __shared__ float Xs[32][64];
    __shared__ float Ms[32][64];
    int b = blockIdx.x;
    int r0 = blockIdx.y * 16;
    int tid = threadIdx.x;
    int r  = tid >> 4;
    int d0 = (tid & 15) * 4;
    ull accN[2] = {0ull, 0ull}, accD[2] = {0ull, 0ull};

    for (int sc = 0; sc < S; sc += 32) {
        {
            int ss = tid & 31, rr = tid >> 5;
#pragma unroll
            for (int p = 0; p < 2; p++)
                Es[rr + p * 8][ss] = g_SC[((long long)b * R + r0 + rr + p * 8) * S + sc + ss];
        }
        {
            int d = tid & 63, s0 = tid >> 6;
#pragma unroll
            for (int p = 0; p < 8; p++) {
                int ss = s0 + p * 4;
                long long gidx = ((long long)b * S + sc + ss) * D + d;
                int mk = xm[gidx];
                float x = xv[gidx];
                Xs[ss][d] = mk ? x : 0.f;
                Ms[ss][d] = mk ? 1.f : 0.f;
            }
        }
        __syncthreads();
#pragma unroll 4
        for (int ss = 0; ss < 32; ss++) {
            ull ee = pk2(Es[r][ss], Es[r][ss]);
            ulonglong2 X0 = *(const ulonglong2*)&Xs[ss][d0];
            ulonglong2 M0 = *(const ulonglong2*)&Ms[ss][d0];
            accN[0] = fma2(ee, X0.x, accN[0]);
            accN[1] = fma2(ee, X0.y, accN[1]);
            accD[0] = fma2(ee, M0.x, accD[0]);
            accD[1] = fma2(ee, M0.y, accD[1]);
        }
        __syncthreads();
    }
    float2 n0 = upk2(accN[0]), n1 = upk2(accN[1]);
    float2 dd0 = upk2(accD[0]), dd1 = upk2(accD[1]);
    float4 o;
    o.x = n0.x / dd0.x; o.y = n0.y / dd0.y;
    o.z = n1.x / dd1.x; o.w = n1.y / dd1.y;
    *(float4*)&g_enc[((long long)b * R + r0 + r) * D + d0] = o;
}

// ---------------- gi tile compute (inside k_gru, barrier shadow) ------------
// gi_s[row][b] = bihs[row] + Wih_row . enc[b][tsrc]   (12 rows x 32 batches)
__device__ __forceinline__ void gi_compute(float (*gi_s)[33],
                                           const float (*Wis)[64],
                                           const float* bihs, int tsrc, int tid)
{
    for (int u = tid; u < 384; u += 256) {
        int row = u >> 5, b = u & 31;
        const float4* er = (const float4*)&g_enc[((long long)b * R + tsrc) * D];
        const float4* wr = (const float4*)&Wis[row][0];
        ull a0 = 0ull, a1 = 0ull;
#pragma unroll
        for (int i = 0; i < 16; i++) {
            float4 e4 = er[i];
            float4 w4 = wr[i];
            a0 = fma2(pk2(w4.x, w4.y), pk2(e4.x, e4.y), a0);
            a1 = fma2(pk2(w4.z, w4.w), pk2(e4.z, e4.w), a1);
        }
        float2 f0 = upk2(a0), f1 = upk2(a1);
        gi_s[row][b] = f0.x + f0.y + f1.x + f1.y + bihs[row];
    }
}

// ---------------- 4) persistent bidirectional GRU (v4) -----------------------
// 128 CTAs (64/dir) x 256 threads. R5-proven single-counter barrier, but the
// wait is now productive: gi[t+1] is computed by all threads between the
// arrival atomic and the spin. hold carried in-register; adaptive-backoff poll.
__global__ void __launch_bounds__(256, 1)
k_gru(const float* __restrict__ Whh_f, const float* __restrict__ bhh_f,
      const float* __restrict__ Whh_b, const float* __restrict__ bhh_b,
      const float* __restrict__ Wih_f, const float* __restrict__ bih_f,
      const float* __restrict__ Wih_b, const float* __restrict__ bih_b,
      float* __restrict__ out)
{
    int bid = blockIdx.x;
    int dir = bid >> 6;
    int grp = bid & 63;
    int j0  = grp * 4;
    const float* Whh = dir ? Whh_b : Whh_f;
    const float* bhh = dir ? bhh_b : bhh_f;
    const float* Wih = dir ? Wih_b : Wih_f;
    const float* bih = dir ? bih_b : bih_f;
    int tid  = threadIdx.x;
    int w    = tid >> 5;   // warp 0..7 : k-slice; for tid<128 also = column
    int lane = tid & 31;   // batch

    __shared__ float4 Ws4[12][64];                 // Whh slice, 12 KB
    __shared__ ull    part[8 * 12 * 32];           // partial sums, 24 KB
    __shared__ __align__(16) float Wis[12][64];    // Wih slice, 3 KB
    __shared__ float  gi_s[2][12][33];             // gi double buffer, 3.2 KB
    __shared__ float  bihs[12];

    for (int i = tid; i < 12 * 64; i += 256) {
        int row = i >> 6, k4 = i & 63;
        int g = row >> 2, c = row & 3;
        Ws4[row][k4] = ((const float4*)(Whh + (long long)(g * H + j0 + c) * H))[k4];
    }
    for (int i = tid; i < 12 * 64; i += 256) {
        int row = i >> 6, d = i & 63;
        int g = row >> 2, c = row & 3;
        Wis[row][d] = Wih[(long long)(g * H + j0 + c) * D + d];
    }
    if (tid < 12) bihs[tid] = bih[(tid >> 2) * H + j0 + (tid & 3)];
    float br = 0.f, bz = 0.f, bn = 0.f;
    if (tid < 128) {
        br = bhh[0 * H + j0 + w];
        bz = bhh[1 * H + j0 + w];
        bn = bhh[2 * H + j0 + w];
    }
    __syncthreads();
    // gi for t=0 (tsrc: fwd 0, bwd R-1)
    gi_compute(gi_s[0], Wis, bihs, dir ? (R - 1) : 0, tid);
    __syncthreads();

    volatile int* barp = (volatile int*)&g_bar[dir];
    float hold = 0.f;   // h(0) = 0; carried in-register thereafter (own column)

    for (int t = 0; t < R; t++) {
        int par = t & 1;
        const float4* hg = &g_h[dir][par][0];

        // --- accumulate over this warp's k-slice straight from L2 ----------
        ull acc[12];
#pragma unroll
        for (int rr = 0; rr < 12; rr++) acc[rr] = 0ull;
#pragma unroll
        for (int q = 0; q < 8; q++) {
            int k4 = w * 8 + q;
            float4 hv4 = __ldcg(&hg[k4 * 32 + lane]);
            ull h01 = pk2(hv4.x, hv4.y);
            ull h23 = pk2(hv4.z, hv4.w);
#pragma unroll
            for (int rr = 0; rr < 12; rr++) {
                ulonglong2 wv = *(const ulonglong2*)&Ws4[rr][k4];
                acc[rr] = fma2(wv.x, h01, acc[rr]);
                acc[rr] = fma2(wv.y, h23, acc[rr]);
            }
        }
#pragma unroll
        for (int rr = 0; rr < 12; rr++)
            part[w * 384 + rr * 32 + lane] = acc[rr];
        __syncthreads();

        // --- reduce + activation (threads 0..127; col = w) -----------------
        if (tid < 128) {
            ull sr = 0ull, sz = 0ull, sn = 0ull;
#pragma unroll
            for (int ww = 0; ww < 8; ww++) {
                sr = add2(sr, part[ww * 384 + (0 + w) * 32 + lane]);
                sz = add2(sz, part[ww * 384 + (4 + w) * 32 + lane]);
                sn = add2(sn, part[ww * 384 + (8 + w) * 32 + lane]);
            }
            float2 fr = upk2(sr), fz = upk2(sz), fn = upk2(sn);
            float ar = fr.x + fr.y, az = fz.x + fz.y, an = fn.x + fn.y;

            float gir = gi_s[par][0 + w][lane];
            float giz = gi_s[par][4 + w][lane];
            float gin = gi_s[par][8 + w][lane];

            float er2 = __expf(-(gir + ar + br));
            float rr  = __fdividef(1.f, 1.f + er2);
            float ez  = __expf(-(giz + az + bz));
            float zz  = __fdividef(1.f, 1.f + ez);
            float xx  = gin + rr * (an + bn);
            xx = fminf(fmaxf(xx, -15.f), 15.f);
            float e2  = __expf(2.f * xx);
            float nn  = 1.f - __fdividef(2.f, e2 + 1.f);
            float hn  = (1.f - zz) * nn + zz * hold;
            hold = hn;

            int tout = dir ? (R - 1 - t) : t;
            out[((long long)lane * R + tout) * (2 * H) + dir * H + j0 + w] = hn;

            if (t < R - 1) {
                float* hw = (float*)&g_h[dir][par ^ 1][0];
                __stcg(hw + (grp * 32 + lane) * 4 + w, hn);
            }
        }
        __syncthreads();   // h stores done block-wide; part[]/gi_s safe

        if (t < R - 1) {
            if (tid == 0) {
                __threadfence();                  // publish h before arrival
                atomicAdd(&g_bar[dir], 1);        // arrival == release signal
            }
            // productive barrier shadow: compute gi for t+1
            int tn = t + 1;
            gi_compute(gi_s[par ^ 1], Wis, bihs, dir ? (R - 1 - tn) : tn, tid);
            if (tid == 0) {
                int target = 64 * (t + 1);
                int vv;
                while ((vv = *barp) < target) {
                    if (target - vv > 2) __nanosleep(64);   // light backoff
                }
            }
            __syncthreads();
        }
    }
}

// ---------------- launcher -------------------------------------------------
extern "C" void kernel_launch(void* const* d_in, const int* in_sizes, int n_in,
                              void* d_out, int out_size)
{
    const float* x_vals     = (const float*)d_in[0];
    const int*   x_mask     = (const int*)  d_in[1];
    const float* time_steps = (const float*)d_in[2];
    const float* query_t    = (const float*)d_in[3];
    const float* Wq         = (const float*)d_in[4];
    const float* bq         = (const float*)d_in[5];
    const float* Wk         = (const float*)d_in[6];
    const float* bk         = (const float*)d_in[7];
    const float* w_per      = (const float*)d_in[8];
    const float* b_per      = (const float*)d_in[9];
    const float* w_lin      = (const float*)d_in[10];
    const float* b_lin      = (const float*)d_in[11];
    const float* Wih_f      = (const float*)d_in[12];
    const float* Whh_f      = (const float*)d_in[13];
    const float* bih_f      = (const float*)d_in[14];
    const float* bhh_f      = (const float*)d_in[15];
    const float* Wih_b      = (const float*)d_in[16];
    const float* Whh_b      = (const float*)d_in[17];
    const float* bih_b      = (const float*)d_in[18];
    const float* bhh_b      = (const float*)d_in[19];
    float* out = (float*)d_out;

    float *p_emb, *p_Q, *p_Q2, *p_cb, *p_SC;
    cudaGetSymbolAddress((void**)&p_emb, g_emb);
    cudaGetSymbolAddress((void**)&p_Q,   g_Q);
    cudaGetSymbolAddress((void**)&p_Q2,  g_Q2);
    cudaGetSymbolAddress((void**)&p_cb,  g_cb);
    cudaGetSymbolAddress((void**)&p_SC,  g_SC);

    // 1) embeddings (+ h/barrier/cb init)
    k_emb<<<(NROWS * 128 + 255) / 256, 256>>>(time_steps, query_t,
                                              w_per, b_per, w_lin, b_lin);
    // 2) Qtmp = emb_q @ Wq^T + bq ; also cb[r] += Qtmp[r].bk (fused epilogue)
    {
        dim3 g(E / 64, R / 64, 1);
        k_gemm_nt<<<g, 256>>>(p_emb + (long long)B * S * E, Wq, bq, nullptr,
                              bk, p_cb,
                              p_Q, E, E, E, E, 0, 0, 0, 1.0f, 0);
    }
    // 2b) Q2 = Qtmp @ Wk   (folds the K projection into Q)
    {
        dim3 g(E / 64, R / 64);
        k_nn<<<g, 256>>>(p_Q, Wk, p_Q2);
    }
    // 3) SC[b] = exp((Q2 @ emb_k^T + cb[r]) / sqrt(E))   (no K materialized)
    {
        dim3 g(S / 64, R / 64, B);
        k_gemm_nt<<<g, 256>>>(p_Q2, p_emb, nullptr, p_cb, nullptr, nullptr,
                              p_SC, E, E, E, S,
                              0, (long long)S * E, (long long)R * S,
                              0.08838834764831845f, 1);
    }
    // 4) enc_in = (e @ mx) / (e @ m)
    {
        dim3 g(B, R / 16);
        k_enc<<<g, 256>>>(x_vals, x_mask);
    }
    // 5) persistent bidirectional GRU (gi fused inside, in barrier shadow)
    k_gru<<<128, 256>>>(Whh_f, bhh_f, Whh_b, bhh_b,
                        Wih_f, bih_f, Wih_b, bih_b, out);
}

// round 10
// speedup vs baseline: 1.1282x; 1.1282x over previous
#include <cuda_runtime.h>
#include <math.h>

static const int B = 32;
static const int S = 512;
static const int R = 128;
static const int D = 64;
static const int E = 128;
static const int H = 256;
#define NROWS (32*512 + 128)   // B*S + R = 16512

typedef unsigned long long ull;

// ---------------- packed f32x2 helpers (sm_100+) ----------------------------
__device__ __forceinline__ ull fma2(ull a, ull b, ull c) {
    ull d; asm("fma.rn.f32x2 %0,%1,%2,%3;" : "=l"(d) : "l"(a), "l"(b), "l"(c));
    return d;
}
__device__ __forceinline__ ull add2(ull a, ull b) {
    ull d; asm("add.rn.f32x2 %0,%1,%2;" : "=l"(d) : "l"(a), "l"(b));
    return d;
}
__device__ __forceinline__ ull pk2(float x, float y) {
    ull d; asm("mov.b64 %0,{%1,%2};" : "=l"(d) : "f"(x), "f"(y));
    return d;
}
__device__ __forceinline__ float2 upk2(ull d) {
    float2 r; asm("mov.b64 {%0,%1},%2;" : "=f"(r.x), "=f"(r.y) : "l"(d));
    return r;
}
__device__ __forceinline__ void cp4(void* dst, const void* src) {
    unsigned d = (unsigned)__cvta_generic_to_shared(dst);
    asm volatile("cp.async.ca.shared.global [%0],[%1],4;" :: "r"(d), "l"(src));
}

// ---------------- scratch (static device globals) ---------------------------
__device__ float g_emb[NROWS * 128];                 // (B*S + R, E)
__device__ float g_Q[128 * 128];                     // Qtmp (R,E)
__device__ float g_Q2[128 * 128];                    // Q2 = Qtmp @ Wk (R,E)
__device__ float g_cb[128];                          // cb[r] = Qtmp[r].bk
__device__ float g_SC[32 * 128 * 512];               // exp(scores), (B,R,S)
__device__ float g_enc[32 * 128 * 64];               // (B,R,D)
__device__ float4 g_h[2][2][(256/4) * 32];           // [dir][parity][k4*32 + b]
__device__ int   g_bar[2];                           // per-direction step counter

// ---------------- 1) time embedding + state init ----------------------------
__global__ void k_emb(const float* __restrict__ ts, const float* __restrict__ qt,
                      const float* __restrict__ w_per, const float* __restrict__ b_per,
                      const float* __restrict__ w_lin, const float* __restrict__ b_lin)
{
    int idx = blockIdx.x * blockDim.x + threadIdx.x;
    if (idx < 2048) {                       // zero h(0) for both dirs (parity 0)
        g_h[0][0][idx] = make_float4(0.f, 0.f, 0.f, 0.f);
        g_h[1][0][idx] = make_float4(0.f, 0.f, 0.f, 0.f);
    }
    if (idx < 128) g_cb[idx] = 0.f;
    if (idx < 2)   g_bar[idx] = 0;
    if (idx >= NROWS * 128) return;
    int row = idx >> 7;
    int e   = idx & 127;
    float t = (row < B * S) ? ts[row] : qt[row - B * S];
    float v;
    if (e == 0) v = fmaf(t, w_lin[0], b_lin[0]);
    else        v = __sinf(fmaf(t, w_per[e - 1], b_per[e - 1]));
    g_emb[idx] = v;
}

// ---------------- 2) C = op(alpha*(A @ B^T + rbias[m]) + bias[n]) ------------
// op = exp() when doexp. Optionally accumulates cbout[m] += C[m,:].dotv via
// atomics (folds cb = Q.bk into the Q projection). 64x64 tile, k-chunk 16,
// 256 thr, cp.async double-buffer.
__global__ void __launch_bounds__(256)
k_gemm_nt(const float* __restrict__ Ag, const float* __restrict__ Bg,
          const float* __restrict__ bias, const float* __restrict__ rbias,
          const float* __restrict__ dotv, float* __restrict__ cbout,
          float* __restrict__ Cg,
          int Ksz, int lda, int ldb, int ldc,
          long long strideA, long long strideB, long long strideC,
          float alpha, int doexp)
{
    __shared__ float As[2][16][68];
    __shared__ float Bs[2][16][68];
    const float* A  = Ag + (long long)blockIdx.z * strideA;
    const float* Bm = Bg + (long long)blockIdx.z * strideB;
    float*       C  = Cg + (long long)blockIdx.z * strideC;
    int m0 = blockIdx.y * 64, n0 = blockIdx.x * 64;
    int tid = threadIdx.x;
    int tx = tid & 15, ty = tid >> 4;
    int k = tid & 15, v = tid >> 4;

    ull acc[4][2];
#pragma unroll
    for (int i = 0; i < 4; i++) { acc[i][0] = 0ull; acc[i][1] = 0ull; }

    int nch = Ksz >> 4;
#pragma unroll
    for (int p = 0; p < 4; p++) {
        cp4(&As[0][k][v + p * 16], &A[(long long)(m0 + v + p * 16) * lda + k]);
        cp4(&Bs[0][k][v + p * 16], &Bm[(long long)(n0 + v + p * 16) * ldb + k]);
    }
    asm volatile("cp.async.commit_group;");

    for (int i = 0; i < nch; i++) {
        if (i + 1 < nch) {
            int buf = (i + 1) & 1, kc = (i + 1) * 16;
#pragma unroll
            for (int p = 0; p < 4; p++) {
                cp4(&As[buf][k][v + p * 16], &A[(long long)(m0 + v + p * 16) * lda + kc + k]);
                cp4(&Bs[buf][k][v + p * 16], &Bm[(long long)(n0 + v + p * 16) * ldb + kc + k]);
            }
            asm volatile("cp.async.commit_group;");
            asm volatile("cp.async.wait_group 1;");
        } else {
            asm volatile("cp.async.wait_group 0;");
        }
        __syncthreads();
        int cb2 = i & 1;
#pragma unroll
        for (int kk = 0; kk < 16; kk++) {
            float4 a4 = *(const float4*)&As[cb2][kk][ty * 4];
            ulonglong2 bb = *(const ulonglong2*)&Bs[cb2][kk][tx * 4];
            ull aa;
            aa = pk2(a4.x, a4.x);
            acc[0][0] = fma2(aa, bb.x, acc[0][0]); acc[0][1] = fma2(aa, bb.y, acc[0][1]);
            aa = pk2(a4.y, a4.y);
            acc[1][0] = fma2(aa, bb.x, acc[1][0]); acc[1][1] = fma2(aa, bb.y, acc[1][1]);
            aa = pk2(a4.z, a4.z);
            acc[2][0] = fma2(aa, bb.x, acc[2][0]); acc[2][1] = fma2(aa, bb.y, acc[2][1]);
            aa = pk2(a4.w, a4.w);
            acc[3][0] = fma2(aa, bb.x, acc[3][0]); acc[3][1] = fma2(aa, bb.y, acc[3][1]);
        }
        __syncthreads();
    }
    float4 bv = make_float4(0.f, 0.f, 0.f, 0.f);
    if (bias) bv = *(const float4*)&bias[n0 + tx * 4];
    float4 dv = make_float4(0.f, 0.f, 0.f, 0.f);
    if (dotv) dv = *(const float4*)&dotv[n0 + tx * 4];
#pragma unroll
    for (int i = 0; i < 4; i++) {
        int m = m0 + ty * 4 + i;
        float rba = rbias ? rbias[m] * alpha : 0.f;
        float2 v0 = upk2(acc[i][0]), v1 = upk2(acc[i][1]);
        float4 o;
        o.x = fmaf(v0.x, alpha, bv.x + rba);
        o.y = fmaf(v0.y, alpha, bv.y + rba);
        o.z = fmaf(v1.x, alpha, bv.z + rba);
        o.w = fmaf(v1.y, alpha, bv.w + rba);
        if (dotv) {
            float p = o.x * dv.x + o.y * dv.y + o.z * dv.z + o.w * dv.w;
#pragma unroll
            for (int off = 8; off > 0; off >>= 1)
                p += __shfl_xor_sync(0xffffffffu, p, off);
            if (tx == 0) atomicAdd(&cbout[m], p);
        }
        if (doexp) {
            o.x = __expf(o.x); o.y = __expf(o.y);
            o.z = __expf(o.z); o.w = __expf(o.w);
        }
        *(float4*)&C[(long long)m * ldc + n0 + tx * 4] = o;
    }
}

// ---------------- 2b) Q2 = Qtmp @ Wk  (NN, 128x128x128, grid (2,2)) ---------
__global__ void __launch_bounds__(256)
k_nn(const float* __restrict__ A, const float* __restrict__ Bm,
     float* __restrict__ C)
{
    __shared__ float As[16][68];
    __shared__ float Bs[16][68];
    int m0 = blockIdx.y * 64, n0 = blockIdx.x * 64;
    int tid = threadIdx.x;
    int tx = tid & 15, ty = tid >> 4;

    ull acc[4][2];
#pragma unroll
    for (int i = 0; i < 4; i++) { acc[i][0] = 0ull; acc[i][1] = 0ull; }

    for (int kc = 0; kc < 128; kc += 16) {
        {
            int k = tid & 15, v = tid >> 4;
#pragma unroll
            for (int p = 0; p < 4; p++)
                As[k][v + p * 16] = A[(m0 + v + p * 16) * 128 + kc + k];
            int kr = tid >> 4, nb = (tid & 15) * 4;
            *(float4*)&Bs[kr][nb] = *(const float4*)&Bm[(kc + kr) * 128 + n0 + nb];
        }
        __syncthreads();
#pragma unroll
        for (int kk = 0; kk < 16; kk++) {
            float4 a4 = *(const float4*)&As[kk][ty * 4];
            ulonglong2 bb = *(const ulonglong2*)&Bs[kk][tx * 4];
            ull aa;
            aa = pk2(a4.x, a4.x);
            acc[0][0] = fma2(aa, bb.x, acc[0][0]); acc[0][1] = fma2(aa, bb.y, acc[0][1]);
            aa = pk2(a4.y, a4.y);
            acc[1][0] = fma2(aa, bb.x, acc[1][0]); acc[1][1] = fma2(aa, bb.y, acc[1][1]);
            aa = pk2(a4.z, a4.z);
            acc[2][0] = fma2(aa, bb.x, acc[2][0]); acc[2][1] = fma2(aa, bb.y, acc[2][1]);
            aa = pk2(a4.w, a4.w);
            acc[3][0] = fma2(aa, bb.x, acc[3][0]); acc[3][1] = fma2(aa, bb.y, acc[3][1]);
        }
        __syncthreads();
    }
#pragma unroll
    for (int i = 0; i < 4; i++) {
        int m = m0 + ty * 4 + i;
        float2 v0 = upk2(acc[i][0]), v1 = upk2(acc[i][1]);
        float4 o = make_float4(v0.x, v0.y, v1.x, v1.y);
        *(float4*)&C[m * 128 + n0 + tx * 4] = o;
    }
}

// ---------------- 3) enc_in = (e @ mask*x) / (e @ mask) ----------------------
__global__ void __launch_bounds__(256)
k_enc(const float* __restrict__ xv, const int* __restrict__ xm)
{
    __shared__ float Es[16][33];
    __shared__ float Xs[32][64];
    __shared__ float Ms[32][64];
    int b = blockIdx.x;
    int r0 = blockIdx.y * 16;
    int tid = threadIdx.x;
    int r  = tid >> 4;
    int d0 = (tid & 15) * 4;
    ull accN[2] = {0ull, 0ull}, accD[2] = {0ull, 0ull};

    for (int sc = 0; sc < S; sc += 32) {
        {
            int ss = tid & 31, rr = tid >> 5;
#pragma unroll
            for (int p = 0; p < 2; p++)
                Es[rr + p * 8][ss] = g_SC[((long long)b * R + r0 + rr + p * 8) * S + sc + ss];
        }
        {
            int d = tid & 63, s0 = tid >> 6;
#pragma unroll
            for (int p = 0; p < 8; p++) {
                int ss = s0 + p * 4;
                long long gidx = ((long long)b * S + sc + ss) * D + d;
                int mk = xm[gidx];
                float x = xv[gidx];
                Xs[ss][d] = mk ? x : 0.f;
                Ms[ss][d] = mk ? 1.f : 0.f;
            }
        }
        __syncthreads();
#pragma unroll 4
        for (int ss = 0; ss < 32; ss++) {
            ull ee = pk2(Es[r][ss], Es[r][ss]);
            ulonglong2 X0 = *(const ulonglong2*)&Xs[ss][d0];
            ulonglong2 M0 = *(const ulonglong2*)&Ms[ss][d0];
            accN[0] = fma2(ee, X0.x, accN[0]);
            accN[1] = fma2(ee, X0.y, accN[1]);
            accD[0] = fma2(ee, M0.x, accD[0]);
            accD[1] = fma2(ee, M0.y, accD[1]);
        }
        __syncthreads();
    }
    float2 n0 = upk2(accN[0]), n1 = upk2(accN[1]);
    float2 dd0 = upk2(accD[0]), dd1 = upk2(accD[1]);
    float4 o;
    o.x = n0.x / dd0.x; o.y = n0.y / dd0.y;
    o.z = n1.x / dd1.x; o.w = n1.y / dd1.y;
    *(float4*)&g_enc[((long long)b * R + r0 + r) * D + d0] = o;
}

// ---------------- gi tile compute (inside k_gru, barrier shadow) ------------
// gi_s[row][b] = bihs[row] + Wih_row . enc[b][tsrc]   (12 rows x 32 batches)
// Executed by threads [first, 256): u strided by (256-first).
__device__ __forceinline__ void gi_compute(float (*gi_s)[33],
                                           const float (*Wis)[64],
                                           const float* bihs, int tsrc,
                                           int tid, int first)
{
    int stride = 256 - first;
    for (int u = tid - first; u < 384; u += stride) {
        int row = u >> 5, b = u & 31;
        const float4* er = (const float4*)&g_enc[((long long)b * R + tsrc) * D];
        const float4* wr = (const float4*)&Wis[row][0];
        ull a0 = 0ull, a1 = 0ull;
#pragma unroll
        for (int i = 0; i < 16; i++) {
            float4 e4 = er[i];
            float4 w4 = wr[i];
            a0 = fma2(pk2(w4.x, w4.y), pk2(e4.x, e4.y), a0);
            a1 = fma2(pk2(w4.z, w4.w), pk2(e4.z, e4.w), a1);
        }
        float2 f0 = upk2(a0), f1 = upk2(a1);
        gi_s[row][b] = f0.x + f0.y + f1.x + f1.y + bihs[row];
    }
}

// ---------------- 4) persistent bidirectional GRU (v5) -----------------------
// 128 CTAs (64/dir) x 256 threads. R8-proven single-counter barrier (plain
// spin, arrival==release). Barrier shadow is productive AND off the critical
// path: tid0 polls immediately after its arrival atomic while threads >=32
// compute gi[t+1] and threads <128 store out[t]. hold carried in-register.
__global__ void __launch_bounds__(256, 1)
k_gru(const float* __restrict__ Whh_f, const float* __restrict__ bhh_f,
      const float* __restrict__ Whh_b, const float* __restrict__ bhh_b,
      const float* __restrict__ Wih_f, const float* __restrict__ bih_f,
      const float* __restrict__ Wih_b, const float* __restrict__ bih_b,
      float* __restrict__ out)
{
    int bid = blockIdx.x;
    int dir = bid >> 6;
    int grp = bid & 63;
    int j0  = grp * 4;
    const float* Whh = dir ? Whh_b : Whh_f;
    const float* bhh = dir ? bhh_b : bhh_f;
    const float* Wih = dir ? Wih_b : Wih_f;
    const float* bih = dir ? bih_b : bih_f;
    int tid  = threadIdx.x;
    int w    = tid >> 5;   // warp 0..7 : k-slice; for tid<128 also = column
    int lane = tid & 31;   // batch

    __shared__ float4 Ws4[12][64];                 // Whh slice, 12 KB
    __shared__ ull    part[8 * 12 * 32];           // partial sums, 24 KB
    __shared__ __align__(16) float Wis[12][64];    // Wih slice, 3 KB
    __shared__ float  gi_s[2][12][33];             // gi double buffer, 3.2 KB
    __shared__ float  bihs[12];

    for (int i = tid; i < 12 * 64; i += 256) {
        int row = i >> 6, k4 = i & 63;
        int g = row >> 2, c = row & 3;
        Ws4[row][k4] = ((const float4*)(Whh + (long long)(g * H + j0 + c) * H))[k4];
    }
    for (int i = tid; i < 12 * 64; i += 256) {
        int row = i >> 6, d = i & 63;
        int g = row >> 2, c = row & 3;
        Wis[row][d] = Wih[(long long)(g * H + j0 + c) * D + d];
    }
    if (tid < 12) bihs[tid] = bih[(tid >> 2) * H + j0 + (tid & 3)];
    float br = 0.f, bz = 0.f, bn = 0.f;
    if (tid < 128) {
        br = bhh[0 * H + j0 + w];
        bz = bhh[1 * H + j0 + w];
        bn = bhh[2 * H + j0 + w];
    }
    __syncthreads();
    // gi for t=0 (tsrc: fwd 0, bwd R-1), computed by all 256 threads
    gi_compute(gi_s[0], Wis, bihs, dir ? (R - 1) : 0, tid, 0);
    __syncthreads();

    volatile int* barp = (volatile int*)&g_bar[dir];
    float hold = 0.f;   // h(0) = 0; carried in-register thereafter (own column)

    for (int t = 0; t < R; t++) {
        int par = t & 1;
        const float4* hg = &g_h[dir][par][0];

        // --- accumulate over this warp's k-slice straight from L2 ----------
        ull acc[12];
#pragma unroll
        for (int rr = 0; rr < 12; rr++) acc[rr] = 0ull;
#pragma unroll
        for (int q = 0; q < 8; q++) {
            int k4 = w * 8 + q;
            float4 hv4 = __ldcg(&hg[k4 * 32 + lane]);
            ull h01 = pk2(hv4.x, hv4.y);
            ull h23 = pk2(hv4.z, hv4.w);
#pragma unroll
            for (int rr = 0; rr < 12; rr++) {
                ulonglong2 wv = *(const ulonglong2*)&Ws4[rr][k4];
                acc[rr] = fma2(wv.x, h01, acc[rr]);
                acc[rr] = fma2(wv.y, h23, acc[rr]);
            }
        }
#pragma unroll
        for (int rr = 0; rr < 12; rr++)
            part[w * 384 + rr * 32 + lane] = acc[rr];
        __syncthreads();

        // --- reduce + activation (threads 0..127; col = w) -----------------
        float hn = 0.f;
        if (tid < 128) {
            ull sr = 0ull, sz = 0ull, sn = 0ull;
#pragma unroll
            for (int ww = 0; ww < 8; ww++) {
                sr = add2(sr, part[ww * 384 + (0 + w) * 32 + lane]);
                sz = add2(sz, part[ww * 384 + (4 + w) * 32 + lane]);
                sn = add2(sn, part[ww * 384 + (8 + w) * 32 + lane]);
            }
            float2 fr = upk2(sr), fz = upk2(sz), fn = upk2(sn);
            float ar = fr.x + fr.y, az = fz.x + fz.y, an = fn.x + fn.y;

            float gir = gi_s[par][0 + w][lane];
            float giz = gi_s[par][4 + w][lane];
            float gin = gi_s[par][8 + w][lane];

            float er2 = __expf(-(gir + ar + br));
            float rr  = __fdividef(1.f, 1.f + er2);
            float ez  = __expf(-(giz + az + bz));
            float zz  = __fdividef(1.f, 1.f + ez);
            float xx  = gin + rr * (an + bn);
            xx = fminf(fmaxf(xx, -15.f), 15.f);
            float e2  = __expf(2.f * xx);
            float nn  = 1.f - __fdividef(2.f, e2 + 1.f);
            hn = (1.f - zz) * nn + zz * hold;
            hold = hn;

            if (t < R - 1) {        // publish h FIRST (critical path)
                float* hw = (float*)&g_h[dir][par ^ 1][0];
                __stcg(hw + (grp * 32 + lane) * 4 + w, hn);
            }
        }
        __syncthreads();   // all h stores issued block-wide

        if (t < R - 1) {
            // arrival first (tid0), then overlap shadow work with the wait
            if (tid == 0) {
                __threadfence();                  // order h before arrival
                atomicAdd(&g_bar[dir], 1);        // arrival == release signal
            }
            // shadow: out store for this step (threads 0..127)
            if (tid < 128) {
                int tout = dir ? (R - 1 - t) : t;
                out[((long long)lane * R + tout) * (2 * H) + dir * H + j0 + w] = hn;
            }
            // shadow: gi for t+1 (threads 32..255; warp0 stays light for poll)
            int tn = t + 1;
            if (tid >= 32)
                gi_compute(gi_s[par ^ 1], Wis, bihs,
                           dir ? (R - 1 - tn) : tn, tid, 32);
            // tid0 polls concurrently with the shadow work above
            if (tid == 0) {
                int target = 64 * (t + 1);
                while (*barp < target) { }
            }
            __syncthreads();
        } else {
            if (tid < 128) {
                int tout = dir ? (R - 1 - t) : t;
                out[((long long)lane * R + tout) * (2 * H) + dir * H + j0 + w] = hn;
            }
        }
    }
}

// ---------------- launcher -------------------------------------------------
extern "C" void kernel_launch(void* const* d_in, const int* in_sizes, int n_in,
                              void* d_out, int out_size)
{
    const float* x_vals     = (const float*)d_in[0];
    const int*   x_mask     = (const int*)  d_in[1];
    const float* time_steps = (const float*)d_in[2];
    const float* query_t    = (const float*)d_in[3];
    const float* Wq         = (const float*)d_in[4];
    const float* bq         = (const float*)d_in[5];
    const float* Wk         = (const float*)d_in[6];
    const float* bk         = (const float*)d_in[7];
    const float* w_per      = (const float*)d_in[8];
    const float* b_per      = (const float*)d_in[9];
    const float* w_lin      = (const float*)d_in[10];
    const float* b_lin      = (const float*)d_in[11];
    const float* Wih_f      = (const float*)d_in[12];
    const float* Whh_f      = (const float*)d_in[13];
    const float* bih_f      = (const float*)d_in[14];
    const float* bhh_f      = (const float*)d_in[15];
    const float* Wih_b      = (const float*)d_in[16];
    const float* Whh_b      = (const float*)d_in[17];
    const float* bih_b      = (const float*)d_in[18];
    const float* bhh_b      = (const float*)d_in[19];
    float* out = (float*)d_out;

    float *p_emb, *p_Q, *p_Q2, *p_cb, *p_SC;
    cudaGetSymbolAddress((void**)&p_emb, g_emb);
    cudaGetSymbolAddress((void**)&p_Q,   g_Q);
    cudaGetSymbolAddress((void**)&p_Q2,  g_Q2);
    cudaGetSymbolAddress((void**)&p_cb,  g_cb);
    cudaGetSymbolAddress((void**)&p_SC,  g_SC);

    // 1) embeddings (+ h/barrier/cb init)
    k_emb<<<(NROWS * 128 + 255) / 256, 256>>>(time_steps, query_t,
                                              w_per, b_per, w_lin, b_lin);
    // 2) Qtmp = emb_q @ Wq^T + bq ; also cb[r] += Qtmp[r].bk (fused epilogue)
    {
        dim3 g(E / 64, R / 64, 1);
        k_gemm_nt<<<g, 256>>>(p_emb + (long long)B * S * E, Wq, bq, nullptr,
                              bk, p_cb,
                              p_Q, E, E, E, E, 0, 0, 0, 1.0f, 0);
    }
    // 2b) Q2 = Qtmp @ Wk   (folds the K projection into Q)
    {
        dim3 g(E / 64, R / 64);
        k_nn<<<g, 256>>>(p_Q, Wk, p_Q2);
    }
    // 3) SC[b] = exp((Q2 @ emb_k^T + cb[r]) / sqrt(E))   (no K materialized)
    {
        dim3 g(S / 64, R / 64, B);
        k_gemm_nt<<<g, 256>>>(p_Q2, p_emb, nullptr, p_cb, nullptr, nullptr,
                              p_SC, E, E, E, S,
                              0, (long long)S * E, (long long)R * S,
                              0.08838834764831845f, 1);
    }
    // 4) enc_in = (e @ mx) / (e @ m)
    {
        dim3 g(B, R / 16);
        k_enc<<<g, 256>>>(x_vals, x_mask);
    }
    // 5) persistent bidirectional GRU (gi fused, computed in barrier shadow)
    k_gru<<<128, 256>>>(Whh_f, bhh_f, Whh_b, bhh_b,
                        Wih_f, bih_f, Wih_b, bih_b, out);
}

// round 11
// speedup vs baseline: 1.4208x; 1.2593x over previous
#include <cuda_runtime.h>
#include <math.h>

static const int B = 32;
static const int S = 512;
static const int R = 128;
static const int D = 64;
static const int E = 128;
static const int H = 256;
#define NROWS (32*512 + 128)   // B*S + R = 16512

typedef unsigned long long ull;

// ---------------- packed f32x2 helpers (sm_100+) ----------------------------
__device__ __forceinline__ ull fma2(ull a, ull b, ull c) {
    ull d; asm("fma.rn.f32x2 %0,%1,%2,%3;" : "=l"(d) : "l"(a), "l"(b), "l"(c));
    return d;
}
__device__ __forceinline__ ull add2(ull a, ull b) {
    ull d; asm("add.rn.f32x2 %0,%1,%2;" : "=l"(d) : "l"(a), "l"(b));
    return d;
}
__device__ __forceinline__ ull pk2(float x, float y) {
    ull d; asm("mov.b64 %0,{%1,%2};" : "=l"(d) : "f"(x), "f"(y));
    return d;
}
__device__ __forceinline__ float2 upk2(ull d) {
    float2 r; asm("mov.b64 {%0,%1},%2;" : "=f"(r.x), "=f"(r.y) : "l"(d));
    return r;
}
__device__ __forceinline__ void cp4(void* dst, const void* src) {
    unsigned d = (unsigned)__cvta_generic_to_shared(dst);
    asm volatile("cp.async.ca.shared.global [%0],[%1],4;" :: "r"(d), "l"(src));
}

// ---------------- scratch (static device globals) ---------------------------
__device__ float g_emb[NROWS * 128];                 // (B*S + R, E)
__device__ float g_Q[128 * 128];                     // Qtmp (R,E)
__device__ float g_Q2[128 * 128];                    // Q2 = Qtmp @ Wk (R,E)
__device__ float g_cb[128];                          // cb[r] = Qtmp[r].bk
__device__ float g_SC[32 * 128 * 512];               // exp(scores), (B,R,S)
__device__ float g_enc[32 * 128 * 64];               // (B,R,D)
__device__ float g_gi[2][128][768][32];              // [dir][t][row(3H)][batch]
__device__ float4 g_h[2][2][(256/4) * 32];           // [dir][parity][k4*32 + b]
__device__ int   g_bar[2];                           // per-direction step counter

// ---------------- 1) time embedding + state init ----------------------------
__global__ void k_emb(const float* __restrict__ ts, const float* __restrict__ qt,
                      const float* __restrict__ w_per, const float* __restrict__ b_per,
                      const float* __restrict__ w_lin, const float* __restrict__ b_lin)
{
    int idx = blockIdx.x * blockDim.x + threadIdx.x;
    if (idx < 2048) {                       // zero h(0) for both dirs (parity 0)
        g_h[0][0][idx] = make_float4(0.f, 0.f, 0.f, 0.f);
        g_h[1][0][idx] = make_float4(0.f, 0.f, 0.f, 0.f);
    }
    if (idx < 128) g_cb[idx] = 0.f;
    if (idx < 2)   g_bar[idx] = 0;
    if (idx >= NROWS * 128) return;
    int row = idx >> 7;
    int e   = idx & 127;
    float t = (row < B * S) ? ts[row] : qt[row - B * S];
    float v;
    if (e == 0) v = fmaf(t, w_lin[0], b_lin[0]);
    else        v = __sinf(fmaf(t, w_per[e - 1], b_per[e - 1]));
    g_emb[idx] = v;
}

// ---------------- 2) C = op(alpha*(A @ B^T + rbias[m]) + bias[n]) ------------
// op = exp() when doexp. Optionally accumulates cbout[m] += C[m,:].dotv via
// atomics (folds cb = Q.bk into the Q projection). 64x64 tile, k-chunk 16,
// 256 thr, cp.async double-buffer.
__global__ void __launch_bounds__(256)
k_gemm_nt(const float* __restrict__ Ag, const float* __restrict__ Bg,
          const float* __restrict__ bias, const float* __restrict__ rbias,
          const float* __restrict__ dotv, float* __restrict__ cbout,
          float* __restrict__ Cg,
          int Ksz, int lda, int ldb, int ldc,
          long long strideA, long long strideB, long long strideC,
          float alpha, int doexp)
{
    __shared__ float As[2][16][68];
    __shared__ float Bs[2][16][68];
    const float* A  = Ag + (long long)blockIdx.z * strideA;
    const float* Bm = Bg + (long long)blockIdx.z * strideB;
    float*       C  = Cg + (long long)blockIdx.z * strideC;
    int m0 = blockIdx.y * 64, n0 = blockIdx.x * 64;
    int tid = threadIdx.x;
    int tx = tid & 15, ty = tid >> 4;
    int k = tid & 15, v = tid >> 4;

    ull acc[4][2];
#pragma unroll
    for (int i = 0; i < 4; i++) { acc[i][0] = 0ull; acc[i][1] = 0ull; }

    int nch = Ksz >> 4;
#pragma unroll
    for (int p = 0; p < 4; p++) {
        cp4(&As[0][k][v + p * 16], &A[(long long)(m0 + v + p * 16) * lda + k]);
        cp4(&Bs[0][k][v + p * 16], &Bm[(long long)(n0 + v + p * 16) * ldb + k]);
    }
    asm volatile("cp.async.commit_group;");

    for (int i = 0; i < nch; i++) {
        if (i + 1 < nch) {
            int buf = (i + 1) & 1, kc = (i + 1) * 16;
#pragma unroll
            for (int p = 0; p < 4; p++) {
                cp4(&As[buf][k][v + p * 16], &A[(long long)(m0 + v + p * 16) * lda + kc + k]);
                cp4(&Bs[buf][k][v + p * 16], &Bm[(long long)(n0 + v + p * 16) * ldb + kc + k]);
            }
            asm volatile("cp.async.commit_group;");
            asm volatile("cp.async.wait_group 1;");
        } else {
            asm volatile("cp.async.wait_group 0;");
        }
        __syncthreads();
        int cb2 = i & 1;
#pragma unroll
        for (int kk = 0; kk < 16; kk++) {
            float4 a4 = *(const float4*)&As[cb2][kk][ty * 4];
            ulonglong2 bb = *(const ulonglong2*)&Bs[cb2][kk][tx * 4];
            ull aa;
            aa = pk2(a4.x, a4.x);
            acc[0][0] = fma2(aa, bb.x, acc[0][0]); acc[0][1] = fma2(aa, bb.y, acc[0][1]);
            aa = pk2(a4.y, a4.y);
            acc[1][0] = fma2(aa, bb.x, acc[1][0]); acc[1][1] = fma2(aa, bb.y, acc[1][1]);
            aa = pk2(a4.z, a4.z);
            acc[2][0] = fma2(aa, bb.x, acc[2][0]); acc[2][1] = fma2(aa, bb.y, acc[2][1]);
            aa = pk2(a4.w, a4.w);
            acc[3][0] = fma2(aa, bb.x, acc[3][0]); acc[3][1] = fma2(aa, bb.y, acc[3][1]);
        }
        __syncthreads();
    }
    float4 bv = make_float4(0.f, 0.f, 0.f, 0.f);
    if (bias) bv = *(const float4*)&bias[n0 + tx * 4];
    float4 dv = make_float4(0.f, 0.f, 0.f, 0.f);
    if (dotv) dv = *(const float4*)&dotv[n0 + tx * 4];
#pragma unroll
    for (int i = 0; i < 4; i++) {
        int m = m0 + ty * 4 + i;
        float rba = rbias ? rbias[m] * alpha : 0.f;
        float2 v0 = upk2(acc[i][0]), v1 = upk2(acc[i][1]);
        float4 o;
        o.x = fmaf(v0.x, alpha, bv.x + rba);
        o.y = fmaf(v0.y, alpha, bv.y + rba);
        o.z = fmaf(v1.x, alpha, bv.z + rba);
        o.w = fmaf(v1.y, alpha, bv.w + rba);
        if (dotv) {
            float p = o.x * dv.x + o.y * dv.y + o.z * dv.z + o.w * dv.w;
#pragma unroll
            for (int off = 8; off > 0; off >>= 1)
                p += __shfl_xor_sync(0xffffffffu, p, off);
            if (tx == 0) atomicAdd(&cbout[m], p);
        }
        if (doexp) {
            o.x = __expf(o.x); o.y = __expf(o.y);
            o.z = __expf(o.z); o.w = __expf(o.w);
        }
        *(float4*)&C[(long long)m * ldc + n0 + tx * 4] = o;
    }
}

// ---------------- 2b) Q2 = Qtmp @ Wk  (NN, 128x128x128, grid (2,2)) ---------
__global__ void __launch_bounds__(256)
k_nn(const float* __restrict__ A, const float* __restrict__ Bm,
     float* __restrict__ C)
{
    __shared__ float As[16][68];
    __shared__ float Bs[16][68];
    int m0 = blockIdx.y * 64, n0 = blockIdx.x * 64;
    int tid = threadIdx.x;
    int tx = tid & 15, ty = tid >> 4;

    ull acc[4][2];
#pragma unroll
    for (int i = 0; i < 4; i++) { acc[i][0] = 0ull; acc[i][1] = 0ull; }

    for (int kc = 0; kc < 128; kc += 16) {
        {
            int k = tid & 15, v = tid >> 4;
#pragma unroll
            for (int p = 0; p < 4; p++)
                As[k][v + p * 16] = A[(m0 + v + p * 16) * 128 + kc + k];
            int kr = tid >> 4, nb = (tid & 15) * 4;
            *(float4*)&Bs[kr][nb] = *(const float4*)&Bm[(kc + kr) * 128 + n0 + nb];
        }
        __syncthreads();
#pragma unroll
        for (int kk = 0; kk < 16; kk++) {
            float4 a4 = *(const float4*)&As[kk][ty * 4];
            ulonglong2 bb = *(const ulonglong2*)&Bs[kk][tx * 4];
            ull aa;
            aa = pk2(a4.x, a4.x);
            acc[0][0] = fma2(aa, bb.x, acc[0][0]); acc[0][1] = fma2(aa, bb.y, acc[0][1]);
            aa = pk2(a4.y, a4.y);
            acc[1][0] = fma2(aa, bb.x, acc[1][0]); acc[1][1] = fma2(aa, bb.y, acc[1][1]);
            aa = pk2(a4.z, a4.z);
            acc[2][0] = fma2(aa, bb.x, acc[2][0]); acc[2][1] = fma2(aa, bb.y, acc[2][1]);
            aa = pk2(a4.w, a4.w);
            acc[3][0] = fma2(aa, bb.x, acc[3][0]); acc[3][1] = fma2(aa, bb.y, acc[3][1]);
        }
        __syncthreads();
    }
#pragma unroll
    for (int i = 0; i < 4; i++) {
        int m = m0 + ty * 4 + i;
        float2 v0 = upk2(acc[i][0]), v1 = upk2(acc[i][1]);
        float4 o = make_float4(v0.x, v0.y, v1.x, v1.y);
        *(float4*)&C[m * 128 + n0 + tx * 4] = o;
    }
}

// ---------------- 3) enc_in = (e @ mask*x) / (e @ mask) ----------------------
__global__ void __launch_bounds__(256)
k_enc(const float* __restrict__ xv, const int* __restrict__ xm)
{
    __shared__ float Es[16][33];
    __shared__ float Xs[32][64];
    __shared__ float Ms[32][64];
    int b = blockIdx.x;
    int r0 = blockIdx.y * 16;
    int tid = threadIdx.x;
    int r  = tid >> 4;
    int d0 = (tid & 15) * 4;
    ull accN[2] = {0ull, 0ull}, accD[2] = {0ull, 0ull};

    for (int sc = 0; sc < S; sc += 32) {
        {
            int ss = tid & 31, rr = tid >> 5;
#pragma unroll
            for (int p = 0; p < 2; p++)
                Es[rr + p * 8][ss] = g_SC[((long long)b * R + r0 + rr + p * 8) * S + sc + ss];
        }
        {
            int d = tid & 63, s0 = tid >> 6;
#pragma unroll
            for (int p = 0; p < 8; p++) {
                int ss = s0 + p * 4;
                long long gidx = ((long long)b * S + sc + ss) * D + d;
                int mk = xm[gidx];
                float x = xv[gidx];
                Xs[ss][d] = mk ? x : 0.f;
                Ms[ss][d] = mk ? 1.f : 0.f;
            }
        }
        __syncthreads();
#pragma unroll 4
        for (int ss = 0; ss < 32; ss++) {
            ull ee = pk2(Es[r][ss], Es[r][ss]);
            ulonglong2 X0 = *(const ulonglong2*)&Xs[ss][d0];
            ulonglong2 M0 = *(const ulonglong2*)&Ms[ss][d0];
            accN[0] = fma2(ee, X0.x, accN[0]);
            accN[1] = fma2(ee, X0.y, accN[1]);
            accD[0] = fma2(ee, M0.x, accD[0]);
            accD[1] = fma2(ee, M0.y, accD[1]);
        }
        __syncthreads();
    }
    float2 n0 = upk2(accN[0]), n1 = upk2(accN[1]);
    float2 dd0 = upk2(accD[0]), dd1 = upk2(accD[1]);
    float4 o;
    o.x = n0.x / dd0.x; o.y = n0.y / dd0.y;
    o.z = n1.x / dd1.x; o.w = n1.y / dd1.y;
    *(float4*)&g_enc[((long long)b * R + r0 + r) * D + d0] = o;
}

// ---------------- 4) gi[dir][t][row][b] = bih + enc[b][tsrc] . Wih[row] -----
__global__ void __launch_bounds__(256)
k_gi(const float* __restrict__ Wf, const float* __restrict__ bf,
     const float* __restrict__ Wb, const float* __restrict__ bb)
{
    int rc  = blockIdx.x * 96;
    int t   = blockIdx.y;
    int dir = blockIdx.z;
    const float* W  = dir ? Wb : Wf;
    const float* bi = dir ? bb : bf;
    int tsrc = dir ? (R - 1 - t) : t;

    __shared__ float encs[32][68];
    __shared__ float Ws[96][64];
    int tid = threadIdx.x;
    {
        int d = tid & 63, b0 = tid >> 6;
#pragma unroll
        for (int p = 0; p < 8; p++) {
            int b = b0 + p * 4;
            encs[b][d] = g_enc[((long long)b * R + tsrc) * D + d];
        }
    }
    {
        int d = tid & 63, r0 = tid >> 6;
#pragma unroll
        for (int p = 0; p < 24; p++) {
            int rl = r0 + p * 4;
            Ws[rl][d] = W[(long long)(rc + rl) * D + d];
        }
    }
    __syncthreads();
    int b  = tid & 31;
    int rg = tid >> 5;
    ull er[32];
#pragma unroll
    for (int i = 0; i < 16; i++) {
        ulonglong2 v = *(const ulonglong2*)&encs[b][i * 4];
        er[2 * i] = v.x; er[2 * i + 1] = v.y;
    }
#pragma unroll 2
    for (int q = 0; q < 12; q++) {
        int rl = rg * 12 + q;
        ull a0 = 0ull, a1 = 0ull;
#pragma unroll
        for (int i = 0; i < 16; i++) {
            ulonglong2 wv = *(const ulonglong2*)&Ws[rl][i * 4];
            a0 = fma2(wv.x, er[2 * i], a0);
            a1 = fma2(wv.y, er[2 * i + 1], a1);
        }
        float2 f0 = upk2(a0), f1 = upk2(a1);
        g_gi[dir][t][rc + rl][b] = f0.x + f0.y + f1.x + f1.y + bi[rc + rl];
    }
}

// ---------------- 5) persistent bidirectional GRU (R8 + register hold) ------
// 128 CTAs (64/dir) x 256 threads. CTA owns 4 h-columns (12 Whh rows, SMEM).
// k-dim split across 8 warps; each warp streams its own h-slice straight from
// L2 (ld.cg), packed f32x2 FMAs, SMEM partial-sum reduction, single-counter
// atomic barrier (measured fastest across R5..R10 variants). hold carried
// in-register; h published before the out store.
__global__ void __launch_bounds__(256, 1)
k_gru(const float* __restrict__ Whh_f, const float* __restrict__ bhh_f,
      const float* __restrict__ Whh_b, const float* __restrict__ bhh_b,
      float* __restrict__ out)
{
    int bid = blockIdx.x;
    int dir = bid >> 6;
    int grp = bid & 63;
    int j0  = grp * 4;
    const float* Whh = dir ? Whh_b : Whh_f;
    const float* bhh = dir ? bhh_b : bhh_f;
    int tid  = threadIdx.x;
    int w    = tid >> 5;   // warp 0..7 : k-slice; for tid<128 also = column
    int lane = tid & 31;   // batch

    __shared__ float4 Ws4[12][64];            // Whh slice, 12 KB
    __shared__ ull    part[8 * 12 * 32];      // partial sums, 24 KB

    for (int i = tid; i < 12 * 64; i += 256) {
        int row = i >> 6, k4 = i & 63;
        int g = row >> 2, c = row & 3;
        Ws4[row][k4] = ((const float4*)(Whh + (long long)(g * H + j0 + c) * H))[k4];
    }
    float br = 0.f, bz = 0.f, bn = 0.f, gir = 0.f, giz = 0.f, gin = 0.f;
    if (tid < 128) {
        br = bhh[0 * H + j0 + w];
        bz = bhh[1 * H + j0 + w];
        bn = bhh[2 * H + j0 + w];
        gir = __ldcg(&g_gi[dir][0][0 * H + j0 + w][lane]);
        giz = __ldcg(&g_gi[dir][0][1 * H + j0 + w][lane]);
        gin = __ldcg(&g_gi[dir][0][2 * H + j0 + w][lane]);
    }
    __syncthreads();

    volatile int* barp = (volatile int*)&g_bar[dir];
    float hold = 0.f;   // h(0)=0; thereafter carried in-register (own column)

    for (int t = 0; t < R; t++) {
        int par = t & 1;
        const float4* hg = &g_h[dir][par][0];

        // --- accumulate over this warp's k-slice straight from L2 ----------
        ull acc[12];
#pragma unroll
        for (int rr = 0; rr < 12; rr++) acc[rr] = 0ull;
#pragma unroll
        for (int q = 0; q < 8; q++) {
            int k4 = w * 8 + q;
            float4 hv4 = __ldcg(&hg[k4 * 32 + lane]);
            ull h01 = pk2(hv4.x, hv4.y);
            ull h23 = pk2(hv4.z, hv4.w);
#pragma unroll
            for (int rr = 0; rr < 12; rr++) {
                ulonglong2 wv = *(const ulonglong2*)&Ws4[rr][k4];
                acc[rr] = fma2(wv.x, h01, acc[rr]);
                acc[rr] = fma2(wv.y, h23, acc[rr]);
            }
        }
#pragma unroll
        for (int rr = 0; rr < 12; rr++)
            part[w * 384 + rr * 32 + lane] = acc[rr];
        __syncthreads();

        // --- reduce + activation (threads 0..127; col = w) -----------------
        if (tid < 128) {
            ull sr = 0ull, sz = 0ull, sn = 0ull;
#pragma unroll
            for (int ww = 0; ww < 8; ww++) {
                sr = add2(sr, part[ww * 384 + (0 + w) * 32 + lane]);
                sz = add2(sz, part[ww * 384 + (4 + w) * 32 + lane]);
                sn = add2(sn, part[ww * 384 + (8 + w) * 32 + lane]);
            }
            float2 fr = upk2(sr), fz = upk2(sz), fn = upk2(sn);
            float ar = fr.x + fr.y, az = fz.x + fz.y, an = fn.x + fn.y;

            float er2 = __expf(-(gir + ar + br));
            float rr  = __fdividef(1.f, 1.f + er2);
            float ez  = __expf(-(giz + az + bz));
            float zz  = __fdividef(1.f, 1.f + ez);
            float xx  = gin + rr * (an + bn);
            xx = fminf(fmaxf(xx, -15.f), 15.f);
            float e2  = __expf(2.f * xx);
            float nn  = 1.f - __fdividef(2.f, e2 + 1.f);
            float hn  = (1.f - zz) * nn + zz * hold;
            hold = hn;

            if (t < R - 1) {        // publish h FIRST (consumer critical path)
                float* hw = (float*)&g_h[dir][par ^ 1][0];
                __stcg(hw + (grp * 32 + lane) * 4 + w, hn);
            }

            int tout = dir ? (R - 1 - t) : t;
            out[((long long)lane * R + tout) * (2 * H) + dir * H + j0 + w] = hn;

            if (t < R - 1) {
                // prefetch gi for t+1 while waiting on the barrier
                gir = __ldcg(&g_gi[dir][t + 1][0 * H + j0 + w][lane]);
                giz = __ldcg(&g_gi[dir][t + 1][1 * H + j0 + w][lane]);
                gin = __ldcg(&g_gi[dir][t + 1][2 * H + j0 + w][lane]);
            }
        }
        __syncthreads();   // h stores done block-wide; part[] safe for reuse

        if (t < R - 1) {
            if (tid == 0) {
                __threadfence();
                atomicAdd(&g_bar[dir], 1);
                int target = 64 * (t + 1);
                while (*barp < target) { }
            }
            __syncthreads();
        }
    }
}

// ---------------- launcher -------------------------------------------------
extern "C" void kernel_launch(void* const* d_in, const int* in_sizes, int n_in,
                              void* d_out, int out_size)
{
    const float* x_vals     = (const float*)d_in[0];
    const int*   x_mask     = (const int*)  d_in[1];
    const float* time_steps = (const float*)d_in[2];
    const float* query_t    = (const float*)d_in[3];
    const float* Wq         = (const float*)d_in[4];
    const float* bq         = (const float*)d_in[5];
    const float* Wk         = (const float*)d_in[6];
    const float* bk         = (const float*)d_in[7];
    const float* w_per      = (const float*)d_in[8];
    const float* b_per      = (const float*)d_in[9];
    const float* w_lin      = (const float*)d_in[10];
    const float* b_lin      = (const float*)d_in[11];
    const float* Wih_f      = (const float*)d_in[12];
    const float* Whh_f      = (const float*)d_in[13];
    const float* bih_f      = (const float*)d_in[14];
    const float* bhh_f      = (const float*)d_in[15];
    const float* Wih_b      = (const float*)d_in[16];
    const float* Whh_b      = (const float*)d_in[17];
    const float* bih_b      = (const float*)d_in[18];
    const float* bhh_b      = (const float*)d_in[19];
    float* out = (float*)d_out;

    float *p_emb, *p_Q, *p_Q2, *p_cb, *p_SC;
    cudaGetSymbolAddress((void**)&p_emb, g_emb);
    cudaGetSymbolAddress((void**)&p_Q,   g_Q);
    cudaGetSymbolAddress((void**)&p_Q2,  g_Q2);
    cudaGetSymbolAddress((void**)&p_cb,  g_cb);
    cudaGetSymbolAddress((void**)&p_SC,  g_SC);

    // 1) embeddings (+ h/barrier/cb init)
    k_emb<<<(NROWS * 128 + 255) / 256, 256>>>(time_steps, query_t,
                                              w_per, b_per, w_lin, b_lin);
    // 2) Qtmp = emb_q @ Wq^T + bq ; also cb[r] += Qtmp[r].bk (fused epilogue)
    {
        dim3 g(E / 64, R / 64, 1);
        k_gemm_nt<<<g, 256>>>(p_emb + (long long)B * S * E, Wq, bq, nullptr,
                              bk, p_cb,
                              p_Q, E, E, E, E, 0, 0, 0, 1.0f, 0);
    }
    // 2b) Q2 = Qtmp @ Wk   (folds the K projection into Q)
    {
        dim3 g(E / 64, R / 64);
        k_nn<<<g, 256>>>(p_Q, Wk, p_Q2);
    }
    // 3) SC[b] = exp((Q2 @ emb_k^T + cb[r]) / sqrt(E))   (no K materialized)
    {
        dim3 g(S / 64, R / 64, B);
        k_gemm_nt<<<g, 256>>>(p_Q2, p_emb, nullptr, p_cb, nullptr, nullptr,
                              p_SC, E, E, E, S,
                              0, (long long)S * E, (long long)R * S,
                              0.08838834764831845f, 1);
    }
    // 4) enc_in = (e @ mx) / (e @ m)
    {
        dim3 g(B, R / 16);
        k_enc<<<g, 256>>>(x_vals, x_mask);
    }
    // 5) gi for both directions (backward pre-reversed)
    {
        dim3 g(8, R, 2);
        k_gi<<<g, 256>>>(Wih_f, bih_f, Wih_b, bih_b);
    }
    // 6) persistent bidirectional GRU
    k_gru<<<128, 256>>>(Whh_f, bhh_f, Whh_b, bhh_b, out);
}